// round 15
// baseline (speedup 1.0000x reference)
#include <cuda_runtime.h>
#include <cuda_bf16.h>
#include <cuda_fp16.h>
#include <math_constants.h>
#include <cstdint>

// ---------------- problem constants ----------------
#define NN    50000
#define EE    800000
#define ETOT  (EE + NN)     // edges + self loops
#define INC   64
#define HIDC  256
#define HEADS 4
#define OUTC  64
#define GG    64
#define CC    10
#define NEG_SLOPE 0.2f

// ---------------- device scratch (no allocation allowed) ----------------
__device__ __align__(16) __half g_Hh[NN * HIDC];   // transformed features (fp16)
__device__ __align__(16) __half g_X1[NN * HIDC];   // layer1 output (residual, fp16)
__device__ __align__(16) __half g_XR[NN * HIDC];   // layer3 output + residual (fp16)
__device__ float g_ssrc[NN * HEADS];
__device__ float g_sdst[NN * HEADS];
__device__ unsigned g_maxenc[3 * HEADS];   // per-layer per-head encoded max(ssrc)
__device__ int   g_rowptr[NN + 1];
__device__ int   g_deg[NN];
__device__ __align__(16) int g_pos[ETOT + 4];  // within-node position (from hist)
__device__ int   g_srcs[ETOT];
__device__ float g_pooled[GG * HIDC];
__device__ float g_cnt[GG];

// bf16 operands for tensor-core GEMM (A single bf16, W split hi/lo)
__device__ __nv_bfloat16 g_Axh[NN * HIDC];   // activation bf16
__device__ __nv_bfloat16 g_Bh1[HIDC * INC];  // W1^T hi  [n][k]
__device__ __nv_bfloat16 g_Bl1[HIDC * INC];
__device__ __nv_bfloat16 g_Bh2[HIDC * HIDC];
__device__ __nv_bfloat16 g_Bl2[HIDC * HIDC];
__device__ __nv_bfloat16 g_Bh3[HIDC * HIDC];
__device__ __nv_bfloat16 g_Bl3[HIDC * HIDC];

// ---------------- PTX helpers (sm_80-compatible: mma.sync / ldmatrix / cp.async) --
__device__ __forceinline__ uint32_t smem_to_u32(const void* p) {
    uint32_t a;
    asm("{ .reg .u64 t; cvta.to.shared.u64 t, %1; cvt.u32.u64 %0, t; }"
        : "=r"(a) : "l"(p));
    return a;
}
__device__ __forceinline__ void cp16(uint32_t dst, const void* src, uint32_t srcsize) {
    asm volatile("cp.async.cg.shared.global [%0], [%1], 16, %2;"
                 :: "r"(dst), "l"(src), "r"(srcsize));
}
#define CP_COMMIT() asm volatile("cp.async.commit_group;" ::: "memory")
#define CP_WAIT(n)  asm volatile("cp.async.wait_group %0;" :: "n"(n) : "memory")

__device__ __forceinline__ void ldm4(uint32_t* r, uint32_t addr) {
    asm volatile("ldmatrix.sync.aligned.m8n8.x4.shared.b16 {%0,%1,%2,%3}, [%4];"
        : "=r"(r[0]), "=r"(r[1]), "=r"(r[2]), "=r"(r[3]) : "r"(addr));
}
__device__ __forceinline__ void mma16816(float* c, const uint32_t* a,
                                         uint32_t b0, uint32_t b1) {
    asm volatile("mma.sync.aligned.m16n8k16.row.col.f32.bf16.bf16.f32 "
        "{%0,%1,%2,%3}, {%4,%5,%6,%7}, {%8,%9}, {%0,%1,%2,%3};"
        : "+f"(c[0]), "+f"(c[1]), "+f"(c[2]), "+f"(c[3])
        : "r"(a[0]), "r"(a[1]), "r"(a[2]), "r"(a[3]), "r"(b0), "r"(b1));
}

// order-preserving float<->uint encoding for atomicMax
__device__ __forceinline__ unsigned encf(float f) {
    unsigned u = __float_as_uint(f);
    return (u & 0x80000000u) ? ~u : (u | 0x80000000u);
}
__device__ __forceinline__ float decf(unsigned u) {
    return (u & 0x80000000u) ? __uint_as_float(u & 0x7FFFFFFFu)
                             : __uint_as_float(~u);
}

// ---------------- zero / init ----------------
__global__ void zero_kernel(int* deg, float* pooled, float* cnt,
                            unsigned* maxenc) {
    int i = blockIdx.x * blockDim.x + threadIdx.x;
    if (i < NN) deg[i] = 0;
    if (i < GG * HIDC) pooled[i] = 0.0f;
    if (i < GG) cnt[i] = 0.0f;
    if (i < 3 * HEADS) maxenc[i] = 0u;    // below enc of any finite float
}

// ---------------- CSR build: hist emits per-edge position -------------------
__global__ void hist_kernel(const int* __restrict__ ei, int* deg,
                            int* __restrict__ pos) {
    int e = blockIdx.x * blockDim.x + threadIdx.x;
    if (e >= ETOT) return;
    int dst = (e < EE) ? __ldg(&ei[EE + e]) : (e - EE);
    pos[e] = atomicAdd(&deg[dst], 1);
}

__global__ void scan_kernel(const int* __restrict__ deg, int* rowptr) {
    __shared__ int sm[1024];
    int t = threadIdx.x;
    const int CH = (NN + 1023) / 1024;
    int b0 = t * CH;
    int b1 = min(b0 + CH, NN);
    int s = 0;
    for (int i = b0; i < b1; i++) s += deg[i];
    sm[t] = s;
    __syncthreads();
    for (int off = 1; off < 1024; off <<= 1) {
        int v = (t >= off) ? sm[t - off] : 0;
        __syncthreads();
        sm[t] += v;
        __syncthreads();
    }
    int run = (t == 0) ? 0 : sm[t - 1];
    for (int i = b0; i < b1; i++) { rowptr[i] = run; run += deg[i]; }
    if (t == 1023) rowptr[NN] = sm[1023];
}

// atomic-free scatter, 4 edges/thread (EE % 4 == 0, so src/dst halves align)
__global__ void scatter_kernel(const int* __restrict__ ei,
                               const int* __restrict__ rowptr,
                               const int* __restrict__ pos,
                               int* __restrict__ srcs) {
    int e0 = (blockIdx.x * blockDim.x + threadIdx.x) * 4;
    if (e0 >= ETOT) return;
    int4 p4 = *(const int4*)(pos + e0);
    int pj[4] = {p4.x, p4.y, p4.z, p4.w};
    int sj[4], dj[4];
    if (e0 + 3 < EE) {
        int4 s4 = *(const int4*)(ei + e0);
        int4 d4 = *(const int4*)(ei + EE + e0);
        sj[0] = s4.x; sj[1] = s4.y; sj[2] = s4.z; sj[3] = s4.w;
        dj[0] = d4.x; dj[1] = d4.y; dj[2] = d4.z; dj[3] = d4.w;
    } else {
#pragma unroll
        for (int j = 0; j < 4; j++) {
            int e = e0 + j;
            if (e < EE)        { sj[j] = __ldg(&ei[e]); dj[j] = __ldg(&ei[EE + e]); }
            else if (e < ETOT) { sj[j] = e - EE; dj[j] = e - EE; }
            else               { dj[j] = -1; }
        }
    }
    int rp[4];
#pragma unroll
    for (int j = 0; j < 4; j++)
        if (e0 + j < ETOT && dj[j] >= 0) rp[j] = __ldg(&rowptr[dj[j]]);
#pragma unroll
    for (int j = 0; j < 4; j++)
        if (e0 + j < ETOT && dj[j] >= 0) srcs[rp[j] + pj[j]] = sj[j];
}

// ---------------- fp32 -> bf16 converters ----------------
__global__ void convert_x_kernel(const float* __restrict__ x,
                                 __nv_bfloat16* __restrict__ hi, int n) {
    int i = blockIdx.x * blockDim.x + threadIdx.x;
    if (i >= n) return;
    hi[i] = __float2bfloat16(x[i]);
}

// All three weights in one launch: W[k][n] fp32 -> out[n][k] bf16 hi/lo
#define W1ELEM (INC * HIDC)
#define W23ELEM (HIDC * HIDC)
__global__ void convert_w_all_kernel(const float* __restrict__ W1,
                                     const float* __restrict__ W2,
                                     const float* __restrict__ W3,
                                     __nv_bfloat16* __restrict__ h1,
                                     __nv_bfloat16* __restrict__ l1,
                                     __nv_bfloat16* __restrict__ h2,
                                     __nv_bfloat16* __restrict__ l2,
                                     __nv_bfloat16* __restrict__ h3,
                                     __nv_bfloat16* __restrict__ l3) {
    int idx = blockIdx.x * blockDim.x + threadIdx.x;
    const float* W;
    __nv_bfloat16 *hi, *lo;
    int K, i;
    if (idx < W1ELEM) {
        W = W1; hi = h1; lo = l1; K = INC; i = idx;
    } else if (idx < W1ELEM + W23ELEM) {
        W = W2; hi = h2; lo = l2; K = HIDC; i = idx - W1ELEM;
    } else if (idx < W1ELEM + 2 * W23ELEM) {
        W = W3; hi = h3; lo = l3; K = HIDC; i = idx - W1ELEM - W23ELEM;
    } else return;
    int n = i / K, k = i - n * K;
    float v = W[(size_t)k * HIDC + n];
    __nv_bfloat16 h = __float2bfloat16(v);
    hi[i] = h;
    lo[i] = __float2bfloat16(v - __bfloat162float(h));
}

// ---------------- mma.sync 2-pass GEMM: C = Ah*(Bh+Bl), fp16 output ----------
// BM=128 BN=128 BK=64, double-buffered cp.async, 8 warps (2m x 4n), 64x32/warp.
// stage: Ah(16K) Bh(16K) Bl(16K) = 48KB; 2 stages = 96KB -> 2 CTAs/SM.
__global__ void __launch_bounds__(256, 2)
gemm_mma_kernel(const __nv_bfloat16* __restrict__ Ah,
                const __nv_bfloat16* __restrict__ Bhi,
                const __nv_bfloat16* __restrict__ Blo,
                __half* __restrict__ Ch, int K) {
    extern __shared__ char smem[];
    uint32_t sbase = smem_to_u32(smem);
    const int tid = threadIdx.x;
    const int lane = tid & 31, wid = tid >> 5;
    const int warp_m = wid & 1;
    const int warp_n = wid >> 1;
    const int rowBase = blockIdx.x * 128;
    const int colBase = blockIdx.y * 128;
    const int Kiters = K >> 6;

    float acc[4][4][4];
#pragma unroll
    for (int a = 0; a < 4; a++)
#pragma unroll
        for (int b = 0; b < 4; b++)
#pragma unroll
            for (int c = 0; c < 4; c++) acc[a][b][c] = 0.0f;

    auto load_stage = [&](int s, int kbase) {
        uint32_t st = sbase + s * 49152;
#pragma unroll
        for (int i = 0; i < 4; i++) {
            int p = tid + i * 256;            // 0..1023
            int r = p >> 3, ck = p & 7;
            uint32_t off = (uint32_t)((r * 8 + (ck ^ (r & 7))) * 16);
            int gr = rowBase + r;
            uint32_t sz = (gr < NN) ? 16u : 0u;
            int grc = min(gr, NN - 1);
            size_t ai = (size_t)grc * K + kbase + ck * 8;
            cp16(st + off, Ah + ai, sz);
            size_t bi = (size_t)(colBase + r) * K + kbase + ck * 8;
            cp16(st + 16384 + off, Bhi + bi, 16u);
            cp16(st + 32768 + off, Blo + bi, 16u);
        }
    };

    load_stage(0, 0);
    CP_COMMIT();

    const int rA  = (lane & 7) + ((lane >> 3) & 1) * 8;
    const int cAb = (lane >> 4) & 1;
    const int rB  = (lane & 7) + ((lane >> 4) & 1) * 8;
    const int cBb = (lane >> 3) & 1;

    for (int kt = 0; kt < Kiters; kt++) {
        if (kt + 1 < Kiters) {
            load_stage((kt + 1) & 1, (kt + 1) * 64);
            CP_COMMIT();
            CP_WAIT(1);
        } else {
            CP_WAIT(0);
        }
        __syncthreads();

        uint32_t mb = sbase + (kt & 1) * 49152;
#pragma unroll
        for (int kh = 0; kh < 4; kh++) {
            uint32_t ah[4][4], bh[2][4], bl[2][4];
            int cA = kh * 2 + cAb;
            int cB = kh * 2 + cBb;
#pragma unroll
            for (int mt = 0; mt < 4; mt++) {
                int row = warp_m * 64 + mt * 16 + rA;
                uint32_t ad = mb + (uint32_t)((row * 8 + (cA ^ (row & 7))) * 16);
                ldm4(ah[mt], ad);
            }
#pragma unroll
            for (int nb = 0; nb < 2; nb++) {
                int n = warp_n * 32 + nb * 16 + rB;
                uint32_t bd = mb + 16384 + (uint32_t)((n * 8 + (cB ^ (n & 7))) * 16);
                ldm4(bh[nb], bd);
                ldm4(bl[nb], bd + 16384);
            }
#pragma unroll
            for (int mt = 0; mt < 4; mt++)
#pragma unroll
                for (int nt = 0; nt < 4; nt++) {
                    int nb = nt >> 1, s2 = (nt & 1) * 2;
                    mma16816(acc[mt][nt], ah[mt], bh[nb][s2], bh[nb][s2 + 1]);
                    mma16816(acc[mt][nt], ah[mt], bl[nb][s2], bl[nb][s2 + 1]);
                }
        }
        __syncthreads();
    }

    // ---- epilogue: half2 stores ----
#pragma unroll
    for (int mt = 0; mt < 4; mt++) {
        int r0 = rowBase + warp_m * 64 + mt * 16 + (lane >> 2);
#pragma unroll
        for (int nt = 0; nt < 4; nt++) {
            int c0 = colBase + warp_n * 32 + nt * 8 + (lane & 3) * 2;
            if (r0 < NN)
                *(__half2*)(Ch + (size_t)r0 * HIDC + c0) =
                    __floats2half2_rn(acc[mt][nt][0], acc[mt][nt][1]);
            if (r0 + 8 < NN)
                *(__half2*)(Ch + (size_t)(r0 + 8) * HIDC + c0) =
                    __floats2half2_rn(acc[mt][nt][2], acc[mt][nt][3]);
        }
    }
}

// ---------------- attention scores per node + folded per-head global max -----
__global__ void score_kernel(const __half* __restrict__ Hh,
                             const float* __restrict__ a_s,
                             const float* __restrict__ a_d,
                             float* __restrict__ ssrc,
                             float* __restrict__ sdst,
                             unsigned* __restrict__ maxenc) {
    __shared__ unsigned smx[HEADS];
    int tid = threadIdx.x;
    if (tid < HEADS) smx[tid] = 0u;
    __syncthreads();

    int warp = (blockIdx.x * blockDim.x + tid) >> 5;
    int lane = tid & 31;
    if (warp < NN) {
        uint4 hv = *(const uint4*)(Hh + (size_t)warp * HIDC + lane * 8);
        float2 f0 = __half22float2(((const __half2*)&hv)[0]);
        float2 f1 = __half22float2(((const __half2*)&hv)[1]);
        float2 f2 = __half22float2(((const __half2*)&hv)[2]);
        float2 f3 = __half22float2(((const __half2*)&hv)[3]);
        const float4* sp = (const float4*)(a_s + lane * 8);
        float4 s0 = sp[0], s1 = sp[1];
        const float4* dp = (const float4*)(a_d + lane * 8);
        float4 d0 = dp[0], d1 = dp[1];
        float vs = f0.x * s0.x + f0.y * s0.y + f1.x * s0.z + f1.y * s0.w
                 + f2.x * s1.x + f2.y * s1.y + f3.x * s1.z + f3.y * s1.w;
        float vd = f0.x * d0.x + f0.y * d0.y + f1.x * d0.z + f1.y * d0.w
                 + f2.x * d1.x + f2.y * d1.y + f3.x * d1.z + f3.y * d1.w;
#pragma unroll
        for (int off = 4; off > 0; off >>= 1) {
            vs += __shfl_xor_sync(0xffffffffu, vs, off);
            vd += __shfl_xor_sync(0xffffffffu, vd, off);
        }
        if ((lane & 7) == 0) {
            int head = lane >> 3;
            ssrc[warp * HEADS + head] = vs;
            sdst[warp * HEADS + head] = vd;
            atomicMax(&smx[head], encf(vs));
        }
    }
    __syncthreads();
    if (tid < HEADS && smx[tid] != 0u) atomicMax(&maxenc[tid], smx[tid]);
}

// ---------------- single-pass softmax aggregation (one warp per node) --------
// lane l owns columns [l*8, l*8+8), head = l>>3.
// e <= m0 := lrelu(max_src(ssrc)+sdst), so exp(e-m0) <= 1: no rescale needed.
// mode 0: fp16 out + bf16 oh | mode 2: bf16 oh only | mode 1: fp16 out + resid
__global__ void __launch_bounds__(256)
agg_kernel(const __half* __restrict__ Hh,
           const float* __restrict__ ssrc,
           const float* __restrict__ sdst,
           const unsigned* __restrict__ maxenc,
           const int* __restrict__ rowptr,
           const int* __restrict__ srcs,
           const float* __restrict__ bias,
           const __half* __restrict__ resid,
           __half* __restrict__ out,
           __nv_bfloat16* __restrict__ oh,
           int mode) {
    int nid = (blockIdx.x * blockDim.x + threadIdx.x) >> 5;
    int lane = threadIdx.x & 31;
    if (nid >= NN) return;
    int head = lane >> 3;
    size_t laneoff = (size_t)lane * 8;

    float sd = sdst[nid * HEADS + head];
    float mtv = decf(__ldg(&maxenc[head])) + sd;
    float m0 = (mtv > 0.0f) ? mtv : NEG_SLOPE * mtv;   // upper bound on e
    int beg = rowptr[nid];
    int end = rowptr[nid + 1];

    float denom = 0.0f;
    float4 a0 = make_float4(0.f, 0.f, 0.f, 0.f);
    float4 a1 = make_float4(0.f, 0.f, 0.f, 0.f);

    // depth-1 pipeline: prefetch next edge's src, score, and feature vec
    int srcN = __ldg(&srcs[beg]);
    float ssN = __ldg(&ssrc[srcN * HEADS + head]);
    uint4 hN = *(const uint4*)(Hh + (size_t)srcN * HIDC + laneoff);

    for (int i = beg; i < end; i++) {
        float ss = ssN;
        uint4 hv = hN;
        if (i + 1 < end) {
            srcN = __ldg(&srcs[i + 1]);
            ssN = __ldg(&ssrc[srcN * HEADS + head]);
            hN = *(const uint4*)(Hh + (size_t)srcN * HIDC + laneoff);
        }
        float e = ss + sd;
        e = (e > 0.0f) ? e : NEG_SLOPE * e;
        float w = __expf(e - m0);
        float2 f0 = __half22float2(((const __half2*)&hv)[0]);
        float2 f1 = __half22float2(((const __half2*)&hv)[1]);
        float2 f2 = __half22float2(((const __half2*)&hv)[2]);
        float2 f3 = __half22float2(((const __half2*)&hv)[3]);
        a0.x = fmaf(w, f0.x, a0.x); a0.y = fmaf(w, f0.y, a0.y);
        a0.z = fmaf(w, f1.x, a0.z); a0.w = fmaf(w, f1.y, a0.w);
        a1.x = fmaf(w, f2.x, a1.x); a1.y = fmaf(w, f2.y, a1.y);
        a1.z = fmaf(w, f3.x, a1.z); a1.w = fmaf(w, f3.y, a1.w);
        denom += w;
    }

    float inv = 1.0f / denom;
    long base = (long)nid * HIDC + lane * 8;
    const float4* bp = (const float4*)(bias + lane * 8);
    float4 b0 = bp[0], b1 = bp[1];
    float r[8];
    r[0] = fmaxf(a0.x * inv + b0.x, 0.f);
    r[1] = fmaxf(a0.y * inv + b0.y, 0.f);
    r[2] = fmaxf(a0.z * inv + b0.z, 0.f);
    r[3] = fmaxf(a0.w * inv + b0.w, 0.f);
    r[4] = fmaxf(a1.x * inv + b1.x, 0.f);
    r[5] = fmaxf(a1.y * inv + b1.y, 0.f);
    r[6] = fmaxf(a1.z * inv + b1.z, 0.f);
    r[7] = fmaxf(a1.w * inv + b1.w, 0.f);
    if (mode == 1) {
        uint4 rv = *(const uint4*)(resid + base);
#pragma unroll
        for (int j = 0; j < 4; j++) {
            float2 q = __half22float2(((const __half2*)&rv)[j]);
            r[j * 2]     += q.x;
            r[j * 2 + 1] += q.y;
        }
    }
    if (mode != 2) {
        __align__(16) __half hv2[8];
#pragma unroll
        for (int j = 0; j < 4; j++)
            ((__half2*)hv2)[j] = __floats2half2_rn(r[j * 2], r[j * 2 + 1]);
        *(uint4*)(out + base) = *(uint4*)hv2;
    }
    if (mode != 1) {
        __align__(16) __nv_bfloat16 bv[8];
#pragma unroll
        for (int j = 0; j < 8; j++) bv[j] = __float2bfloat16(r[j]);
        *(uint4*)(oh + base) = *(uint4*)bv;
    }
}

// ---------------- global mean pool (batch is sorted, fp16 input) -------------
#define POOL_CH 256
__global__ void pool_kernel(const __half* __restrict__ xr,
                            const int* __restrict__ batch,
                            float* pooled, float* cnt) {
    __shared__ int sb[POOL_CH];
    int b0 = blockIdx.x * POOL_CH;
    int t = threadIdx.x;
    int nmax = min(POOL_CH, NN - b0);
    if (nmax <= 0) return;
    for (int i = t; i < nmax; i += blockDim.x) sb[i] = batch[b0 + i];
    __syncthreads();

    float acc = 0.0f;
    int gcur = sb[0];
    int cstart = 0;
    for (int i = 0; i < nmax; i++) {
        int g = sb[i];
        if (g != gcur) {
            atomicAdd(&pooled[gcur * HIDC + t], acc);
            if (t == 0) atomicAdd(&cnt[gcur], (float)(i - cstart));
            acc = 0.0f; cstart = i; gcur = g;
        }
        acc += __half2float(xr[(size_t)(b0 + i) * HIDC + t]);
    }
    atomicAdd(&pooled[gcur * HIDC + t], acc);
    if (t == 0) atomicAdd(&cnt[gcur], (float)(nmax - cstart));
}

// ---------------- final FC ----------------
__global__ void fc_kernel(const float* __restrict__ pooled,
                          const float* __restrict__ cnt,
                          const float* __restrict__ fcW,
                          const float* __restrict__ fcb,
                          float* __restrict__ out) {
    int idx = blockIdx.x * blockDim.x + threadIdx.x;
    if (idx >= GG * CC) return;
    int g = idx / CC, c = idx % CC;
    float inv = 1.0f / fmaxf(cnt[g], 1.0f);
    float acc = 0.0f;
    for (int k = 0; k < HIDC; k++)
        acc = fmaf(pooled[g * HIDC + k], fcW[k * CC + c], acc);
    out[idx] = acc * inv + fcb[c];
}

// ---------------- launch ----------------
extern "C" void kernel_launch(void* const* d_in, const int* in_sizes, int n_in,
                              void* d_out, int out_size) {
    const float* x   = (const float*)d_in[0];
    const int*   ei  = (const int*)d_in[1];
    const int*   bat = (const int*)d_in[2];
    const float* W1  = (const float*)d_in[3];
    const float* as1 = (const float*)d_in[4];
    const float* ad1 = (const float*)d_in[5];
    const float* b1  = (const float*)d_in[6];
    const float* W2  = (const float*)d_in[7];
    const float* as2 = (const float*)d_in[8];
    const float* ad2 = (const float*)d_in[9];
    const float* b2  = (const float*)d_in[10];
    const float* W3  = (const float*)d_in[11];
    const float* as3 = (const float*)d_in[12];
    const float* ad3 = (const float*)d_in[13];
    const float* b3  = (const float*)d_in[14];
    const float* fcW = (const float*)d_in[15];
    const float* fcb = (const float*)d_in[16];
    float* out = (float*)d_out;

    float *pSS, *pSD, *pPool, *pCnt;
    int *pRow, *pDeg, *pPos, *pSrc;
    unsigned* pME;
    __half *pHh, *pX1, *pXR;
    __nv_bfloat16 *pAxh, *pBh1, *pBl1, *pBh2, *pBl2, *pBh3, *pBl3;
    cudaGetSymbolAddress((void**)&pHh, g_Hh);
    cudaGetSymbolAddress((void**)&pX1, g_X1);
    cudaGetSymbolAddress((void**)&pXR, g_XR);
    cudaGetSymbolAddress((void**)&pSS, g_ssrc);
    cudaGetSymbolAddress((void**)&pSD, g_sdst);
    cudaGetSymbolAddress((void**)&pME, g_maxenc);
    cudaGetSymbolAddress((void**)&pRow, g_rowptr);
    cudaGetSymbolAddress((void**)&pDeg, g_deg);
    cudaGetSymbolAddress((void**)&pPos, g_pos);
    cudaGetSymbolAddress((void**)&pSrc, g_srcs);
    cudaGetSymbolAddress((void**)&pPool, g_pooled);
    cudaGetSymbolAddress((void**)&pCnt, g_cnt);
    cudaGetSymbolAddress((void**)&pAxh, g_Axh);
    cudaGetSymbolAddress((void**)&pBh1, g_Bh1);
    cudaGetSymbolAddress((void**)&pBl1, g_Bl1);
    cudaGetSymbolAddress((void**)&pBh2, g_Bh2);
    cudaGetSymbolAddress((void**)&pBl2, g_Bl2);
    cudaGetSymbolAddress((void**)&pBh3, g_Bh3);
    cudaGetSymbolAddress((void**)&pBl3, g_Bl3);

    const int GEMM_SMEM = 98304;   // 2 stages x 48KB -> 2 CTAs/SM
    cudaFuncSetAttribute(gemm_mma_kernel,
                         cudaFuncAttributeMaxDynamicSharedMemorySize, GEMM_SMEM);

    // init + CSR build + operand conversion
    zero_kernel<<<(NN + 255) / 256, 256>>>(pDeg, pPool, pCnt, pME);
    hist_kernel<<<(ETOT + 255) / 256, 256>>>(ei, pDeg, pPos);
    scan_kernel<<<1, 1024>>>(pDeg, pRow);
    scatter_kernel<<<(ETOT + 1023) / 1024, 256>>>(ei, pRow, pPos, pSrc);
    convert_x_kernel<<<(NN * INC + 255) / 256, 256>>>(x, pAxh, NN * INC);
    convert_w_all_kernel<<<(W1ELEM + 2 * W23ELEM + 255) / 256, 256>>>(
        W1, W2, W3, pBh1, pBl1, pBh2, pBl2, pBh3, pBl3);

    const int warpBlocks = (NN * 32 + 255) / 256;
    dim3 gemmGrid((NN + 127) / 128, HIDC / 128);

    // layer 1 (K=64)
    gemm_mma_kernel<<<gemmGrid, 256, GEMM_SMEM>>>(pAxh, pBh1, pBl1, pHh, INC);
    score_kernel<<<warpBlocks, 256>>>(pHh, as1, ad1, pSS, pSD, pME + 0);
    agg_kernel<<<warpBlocks, 256>>>(pHh, pSS, pSD, pME + 0, pRow, pSrc, b1, nullptr,
                                    pX1, pAxh, 0);

    // layer 2 (K=256) — bf16 output only
    gemm_mma_kernel<<<gemmGrid, 256, GEMM_SMEM>>>(pAxh, pBh2, pBl2, pHh, HIDC);
    score_kernel<<<warpBlocks, 256>>>(pHh, as2, ad2, pSS, pSD, pME + 4);
    agg_kernel<<<warpBlocks, 256>>>(pHh, pSS, pSD, pME + 4, pRow, pSrc, b2, nullptr,
                                    pX1, pAxh, 2);

    // layer 3 (K=256, + residual with X1)
    gemm_mma_kernel<<<gemmGrid, 256, GEMM_SMEM>>>(pAxh, pBh3, pBl3, pHh, HIDC);
    score_kernel<<<warpBlocks, 256>>>(pHh, as3, ad3, pSS, pSD, pME + 8);
    agg_kernel<<<warpBlocks, 256>>>(pHh, pSS, pSD, pME + 8, pRow, pSrc, b3, pX1,
                                    pXR, nullptr, 1);

    // pool + fc
    pool_kernel<<<(NN + POOL_CH - 1) / POOL_CH, 256>>>(pXR, bat, pPool, pCnt);
    fc_kernel<<<(GG * CC + 255) / 256, 256>>>(pPool, pCnt, fcW, fcb, out);
}

// round 16
// speedup vs baseline: 1.0063x; 1.0063x over previous
#include <cuda_runtime.h>
#include <cuda_bf16.h>
#include <cuda_fp16.h>
#include <math_constants.h>
#include <cstdint>

// ---------------- problem constants ----------------
#define NN    50000
#define EE    800000
#define ETOT  (EE + NN)     // edges + self loops
#define INC   64
#define HIDC  256
#define HEADS 4
#define OUTC  64
#define GG    64
#define CC    10
#define NEG_SLOPE 0.2f

// ---------------- device scratch (no allocation allowed) ----------------
__device__ __align__(16) __half g_Xin[NN * INC];   // input x in fp16
__device__ __align__(16) __half g_Hh[NN * HIDC];   // transformed features (fp16)
__device__ __align__(16) __half g_X1[NN * HIDC];   // layer1 output (resid + GEMM A)
__device__ __align__(16) __half g_X2[NN * HIDC];   // layer2 output (GEMM A)
__device__ __align__(16) __half g_XR[NN * HIDC];   // layer3 output + residual
__device__ float g_ssrc[NN * HEADS];
__device__ float g_sdst[NN * HEADS];
__device__ unsigned g_maxenc[3 * HEADS];   // per-layer per-head encoded max(ssrc)
__device__ int   g_rowptr[NN + 1];
__device__ int   g_deg[NN];
__device__ __align__(16) int g_pos[ETOT + 4];  // within-node position (from hist)
__device__ int   g_srcs[ETOT];
__device__ float g_pooled[GG * HIDC];
__device__ float g_cnt[GG];

// fp16 hi/lo weights for tensor-core GEMM: Wt[n][k]
__device__ __half g_Bh1[HIDC * INC];
__device__ __half g_Bl1[HIDC * INC];
__device__ __half g_Bh2[HIDC * HIDC];
__device__ __half g_Bl2[HIDC * HIDC];
__device__ __half g_Bh3[HIDC * HIDC];
__device__ __half g_Bl3[HIDC * HIDC];

// ---------------- PTX helpers (sm_80-compatible: mma.sync / ldmatrix / cp.async) --
__device__ __forceinline__ uint32_t smem_to_u32(const void* p) {
    uint32_t a;
    asm("{ .reg .u64 t; cvta.to.shared.u64 t, %1; cvt.u32.u64 %0, t; }"
        : "=r"(a) : "l"(p));
    return a;
}
__device__ __forceinline__ void cp16(uint32_t dst, const void* src, uint32_t srcsize) {
    asm volatile("cp.async.cg.shared.global [%0], [%1], 16, %2;"
                 :: "r"(dst), "l"(src), "r"(srcsize));
}
#define CP_COMMIT() asm volatile("cp.async.commit_group;" ::: "memory")
#define CP_WAIT(n)  asm volatile("cp.async.wait_group %0;" :: "n"(n) : "memory")

__device__ __forceinline__ void ldm4(uint32_t* r, uint32_t addr) {
    asm volatile("ldmatrix.sync.aligned.m8n8.x4.shared.b16 {%0,%1,%2,%3}, [%4];"
        : "=r"(r[0]), "=r"(r[1]), "=r"(r[2]), "=r"(r[3]) : "r"(addr));
}
__device__ __forceinline__ void mma16816(float* c, const uint32_t* a,
                                         uint32_t b0, uint32_t b1) {
    asm volatile("mma.sync.aligned.m16n8k16.row.col.f32.f16.f16.f32 "
        "{%0,%1,%2,%3}, {%4,%5,%6,%7}, {%8,%9}, {%0,%1,%2,%3};"
        : "+f"(c[0]), "+f"(c[1]), "+f"(c[2]), "+f"(c[3])
        : "r"(a[0]), "r"(a[1]), "r"(a[2]), "r"(a[3]), "r"(b0), "r"(b1));
}

// order-preserving float<->uint encoding for atomicMax
__device__ __forceinline__ unsigned encf(float f) {
    unsigned u = __float_as_uint(f);
    return (u & 0x80000000u) ? ~u : (u | 0x80000000u);
}
__device__ __forceinline__ float decf(unsigned u) {
    return (u & 0x80000000u) ? __uint_as_float(u & 0x7FFFFFFFu)
                             : __uint_as_float(~u);
}

// ---------------- zero / init ----------------
__global__ void zero_kernel(int* deg, float* pooled, float* cnt,
                            unsigned* maxenc) {
    int i = blockIdx.x * blockDim.x + threadIdx.x;
    if (i < NN) deg[i] = 0;
    if (i < GG * HIDC) pooled[i] = 0.0f;
    if (i < GG) cnt[i] = 0.0f;
    if (i < 3 * HEADS) maxenc[i] = 0u;    // below enc of any finite float
}

// ---------------- CSR build: hist emits per-edge position -------------------
__global__ void hist_kernel(const int* __restrict__ ei, int* deg,
                            int* __restrict__ pos) {
    int e = blockIdx.x * blockDim.x + threadIdx.x;
    if (e >= ETOT) return;
    int dst = (e < EE) ? __ldg(&ei[EE + e]) : (e - EE);
    pos[e] = atomicAdd(&deg[dst], 1);
}

__global__ void scan_kernel(const int* __restrict__ deg, int* rowptr) {
    __shared__ int sm[1024];
    int t = threadIdx.x;
    const int CH = (NN + 1023) / 1024;
    int b0 = t * CH;
    int b1 = min(b0 + CH, NN);
    int s = 0;
    for (int i = b0; i < b1; i++) s += deg[i];
    sm[t] = s;
    __syncthreads();
    for (int off = 1; off < 1024; off <<= 1) {
        int v = (t >= off) ? sm[t - off] : 0;
        __syncthreads();
        sm[t] += v;
        __syncthreads();
    }
    int run = (t == 0) ? 0 : sm[t - 1];
    for (int i = b0; i < b1; i++) { rowptr[i] = run; run += deg[i]; }
    if (t == 1023) rowptr[NN] = sm[1023];
}

// atomic-free scatter: slot = rowptr[dst] + pos[e]
__global__ void scatter_kernel(const int* __restrict__ ei,
                               const int* __restrict__ rowptr,
                               const int* __restrict__ pos,
                               int* __restrict__ srcs) {
    int e = blockIdx.x * blockDim.x + threadIdx.x;
    if (e >= ETOT) return;
    int src, dst;
    if (e < EE) { src = __ldg(&ei[e]); dst = __ldg(&ei[EE + e]); }
    else        { src = e - EE; dst = e - EE; }
    srcs[__ldg(&rowptr[dst]) + __ldg(&pos[e])] = src;
}

// ---------------- fp32 -> fp16 converters ----------------
__global__ void convert_x_kernel(const float* __restrict__ x,
                                 __half* __restrict__ out, int n) {
    int i = blockIdx.x * blockDim.x + threadIdx.x;
    if (i >= n) return;
    out[i] = __float2half_rn(x[i]);
}

// All three weights in one launch: W[k][n] fp32 -> out[n][k] fp16 hi/lo
#define W1ELEM (INC * HIDC)
#define W23ELEM (HIDC * HIDC)
__global__ void convert_w_all_kernel(const float* __restrict__ W1,
                                     const float* __restrict__ W2,
                                     const float* __restrict__ W3,
                                     __half* __restrict__ h1,
                                     __half* __restrict__ l1,
                                     __half* __restrict__ h2,
                                     __half* __restrict__ l2,
                                     __half* __restrict__ h3,
                                     __half* __restrict__ l3) {
    int idx = blockIdx.x * blockDim.x + threadIdx.x;
    const float* W;
    __half *hi, *lo;
    int K, i;
    if (idx < W1ELEM) {
        W = W1; hi = h1; lo = l1; K = INC; i = idx;
    } else if (idx < W1ELEM + W23ELEM) {
        W = W2; hi = h2; lo = l2; K = HIDC; i = idx - W1ELEM;
    } else if (idx < W1ELEM + 2 * W23ELEM) {
        W = W3; hi = h3; lo = l3; K = HIDC; i = idx - W1ELEM - W23ELEM;
    } else return;
    int n = i / K, k = i - n * K;
    float v = W[(size_t)k * HIDC + n];
    __half h = __float2half_rn(v);
    hi[i] = h;
    lo[i] = __float2half_rn(v - __half2float(h));
}

// ---------------- mma.sync 2-pass GEMM: C = A*(Bh+Bl), fp16 in/out ----------
// BM=128 BN=128 BK=64, double-buffered cp.async, 8 warps (2m x 4n), 64x32/warp.
// stage: A(16K) Bh(16K) Bl(16K) = 48KB; 2 stages = 96KB -> 2 CTAs/SM.
__global__ void __launch_bounds__(256, 2)
gemm_mma_kernel(const __half* __restrict__ Ah,
                const __half* __restrict__ Bhi,
                const __half* __restrict__ Blo,
                __half* __restrict__ Ch, int K) {
    extern __shared__ char smem[];
    uint32_t sbase = smem_to_u32(smem);
    const int tid = threadIdx.x;
    const int lane = tid & 31, wid = tid >> 5;
    const int warp_m = wid & 1;
    const int warp_n = wid >> 1;
    const int rowBase = blockIdx.x * 128;
    const int colBase = blockIdx.y * 128;
    const int Kiters = K >> 6;

    float acc[4][4][4];
#pragma unroll
    for (int a = 0; a < 4; a++)
#pragma unroll
        for (int b = 0; b < 4; b++)
#pragma unroll
            for (int c = 0; c < 4; c++) acc[a][b][c] = 0.0f;

    auto load_stage = [&](int s, int kbase) {
        uint32_t st = sbase + s * 49152;
#pragma unroll
        for (int i = 0; i < 4; i++) {
            int p = tid + i * 256;            // 0..1023
            int r = p >> 3, ck = p & 7;
            uint32_t off = (uint32_t)((r * 8 + (ck ^ (r & 7))) * 16);
            int gr = rowBase + r;
            uint32_t sz = (gr < NN) ? 16u : 0u;
            int grc = min(gr, NN - 1);
            size_t ai = (size_t)grc * K + kbase + ck * 8;
            cp16(st + off, Ah + ai, sz);
            size_t bi = (size_t)(colBase + r) * K + kbase + ck * 8;
            cp16(st + 16384 + off, Bhi + bi, 16u);
            cp16(st + 32768 + off, Blo + bi, 16u);
        }
    };

    load_stage(0, 0);
    CP_COMMIT();

    const int rA  = (lane & 7) + ((lane >> 3) & 1) * 8;
    const int cAb = (lane >> 4) & 1;
    const int rB  = (lane & 7) + ((lane >> 4) & 1) * 8;
    const int cBb = (lane >> 3) & 1;

    for (int kt = 0; kt < Kiters; kt++) {
        if (kt + 1 < Kiters) {
            load_stage((kt + 1) & 1, (kt + 1) * 64);
            CP_COMMIT();
            CP_WAIT(1);
        } else {
            CP_WAIT(0);
        }
        __syncthreads();

        uint32_t mb = sbase + (kt & 1) * 49152;
#pragma unroll
        for (int kh = 0; kh < 4; kh++) {
            uint32_t ah[4][4], bh[2][4], bl[2][4];
            int cA = kh * 2 + cAb;
            int cB = kh * 2 + cBb;
#pragma unroll
            for (int mt = 0; mt < 4; mt++) {
                int row = warp_m * 64 + mt * 16 + rA;
                uint32_t ad = mb + (uint32_t)((row * 8 + (cA ^ (row & 7))) * 16);
                ldm4(ah[mt], ad);
            }
#pragma unroll
            for (int nb = 0; nb < 2; nb++) {
                int n = warp_n * 32 + nb * 16 + rB;
                uint32_t bd = mb + 16384 + (uint32_t)((n * 8 + (cB ^ (n & 7))) * 16);
                ldm4(bh[nb], bd);
                ldm4(bl[nb], bd + 16384);
            }
#pragma unroll
            for (int mt = 0; mt < 4; mt++)
#pragma unroll
                for (int nt = 0; nt < 4; nt++) {
                    int nb = nt >> 1, s2 = (nt & 1) * 2;
                    mma16816(acc[mt][nt], ah[mt], bh[nb][s2], bh[nb][s2 + 1]);
                    mma16816(acc[mt][nt], ah[mt], bl[nb][s2], bl[nb][s2 + 1]);
                }
        }
        __syncthreads();
    }

    // ---- epilogue: half2 stores ----
#pragma unroll
    for (int mt = 0; mt < 4; mt++) {
        int r0 = rowBase + warp_m * 64 + mt * 16 + (lane >> 2);
#pragma unroll
        for (int nt = 0; nt < 4; nt++) {
            int c0 = colBase + warp_n * 32 + nt * 8 + (lane & 3) * 2;
            if (r0 < NN)
                *(__half2*)(Ch + (size_t)r0 * HIDC + c0) =
                    __floats2half2_rn(acc[mt][nt][0], acc[mt][nt][1]);
            if (r0 + 8 < NN)
                *(__half2*)(Ch + (size_t)(r0 + 8) * HIDC + c0) =
                    __floats2half2_rn(acc[mt][nt][2], acc[mt][nt][3]);
        }
    }
}

// ---------------- attention scores per node + folded per-head global max -----
__global__ void score_kernel(const __half* __restrict__ Hh,
                             const float* __restrict__ a_s,
                             const float* __restrict__ a_d,
                             float* __restrict__ ssrc,
                             float* __restrict__ sdst,
                             unsigned* __restrict__ maxenc) {
    __shared__ unsigned smx[HEADS];
    int tid = threadIdx.x;
    if (tid < HEADS) smx[tid] = 0u;
    __syncthreads();

    int warp = (blockIdx.x * blockDim.x + tid) >> 5;
    int lane = tid & 31;
    if (warp < NN) {
        uint4 hv = *(const uint4*)(Hh + (size_t)warp * HIDC + lane * 8);
        float2 f0 = __half22float2(((const __half2*)&hv)[0]);
        float2 f1 = __half22float2(((const __half2*)&hv)[1]);
        float2 f2 = __half22float2(((const __half2*)&hv)[2]);
        float2 f3 = __half22float2(((const __half2*)&hv)[3]);
        const float4* sp = (const float4*)(a_s + lane * 8);
        float4 s0 = sp[0], s1 = sp[1];
        const float4* dp = (const float4*)(a_d + lane * 8);
        float4 d0 = dp[0], d1 = dp[1];
        float vs = f0.x * s0.x + f0.y * s0.y + f1.x * s0.z + f1.y * s0.w
                 + f2.x * s1.x + f2.y * s1.y + f3.x * s1.z + f3.y * s1.w;
        float vd = f0.x * d0.x + f0.y * d0.y + f1.x * d0.z + f1.y * d0.w
                 + f2.x * d1.x + f2.y * d1.y + f3.x * d1.z + f3.y * d1.w;
#pragma unroll
        for (int off = 4; off > 0; off >>= 1) {
            vs += __shfl_xor_sync(0xffffffffu, vs, off);
            vd += __shfl_xor_sync(0xffffffffu, vd, off);
        }
        if ((lane & 7) == 0) {
            int head = lane >> 3;
            ssrc[warp * HEADS + head] = vs;
            sdst[warp * HEADS + head] = vd;
            atomicMax(&smx[head], encf(vs));
        }
    }
    __syncthreads();
    if (tid < HEADS && smx[tid] != 0u) atomicMax(&maxenc[tid], smx[tid]);
}

// ---------------- single-pass softmax aggregation (one warp per node) --------
// lane l owns columns [l*8, l*8+8), head = l>>3.
// e <= m0 := lrelu(max_src(ssrc)+sdst), so exp(e-m0) <= 1: no rescale needed.
// mode 0: fp16 out | mode 1: fp16 out + resid
__global__ void __launch_bounds__(256)
agg_kernel(const __half* __restrict__ Hh,
           const float* __restrict__ ssrc,
           const float* __restrict__ sdst,
           const unsigned* __restrict__ maxenc,
           const int* __restrict__ rowptr,
           const int* __restrict__ srcs,
           const float* __restrict__ bias,
           const __half* __restrict__ resid,
           __half* __restrict__ out,
           int mode) {
    int nid = (blockIdx.x * blockDim.x + threadIdx.x) >> 5;
    int lane = threadIdx.x & 31;
    if (nid >= NN) return;
    int head = lane >> 3;
    size_t laneoff = (size_t)lane * 8;

    float sd = sdst[nid * HEADS + head];
    float mtv = decf(__ldg(&maxenc[head])) + sd;
    float m0 = (mtv > 0.0f) ? mtv : NEG_SLOPE * mtv;   // upper bound on e
    int beg = rowptr[nid];
    int end = rowptr[nid + 1];

    float denom = 0.0f;
    float4 a0 = make_float4(0.f, 0.f, 0.f, 0.f);
    float4 a1 = make_float4(0.f, 0.f, 0.f, 0.f);

    // depth-1 pipeline: prefetch next edge's src, score, and feature vec
    int srcN = __ldg(&srcs[beg]);
    float ssN = __ldg(&ssrc[srcN * HEADS + head]);
    uint4 hN = *(const uint4*)(Hh + (size_t)srcN * HIDC + laneoff);

    for (int i = beg; i < end; i++) {
        float ss = ssN;
        uint4 hv = hN;
        if (i + 1 < end) {
            srcN = __ldg(&srcs[i + 1]);
            ssN = __ldg(&ssrc[srcN * HEADS + head]);
            hN = *(const uint4*)(Hh + (size_t)srcN * HIDC + laneoff);
        }
        float e = ss + sd;
        e = (e > 0.0f) ? e : NEG_SLOPE * e;
        float w = __expf(e - m0);
        float2 f0 = __half22float2(((const __half2*)&hv)[0]);
        float2 f1 = __half22float2(((const __half2*)&hv)[1]);
        float2 f2 = __half22float2(((const __half2*)&hv)[2]);
        float2 f3 = __half22float2(((const __half2*)&hv)[3]);
        a0.x = fmaf(w, f0.x, a0.x); a0.y = fmaf(w, f0.y, a0.y);
        a0.z = fmaf(w, f1.x, a0.z); a0.w = fmaf(w, f1.y, a0.w);
        a1.x = fmaf(w, f2.x, a1.x); a1.y = fmaf(w, f2.y, a1.y);
        a1.z = fmaf(w, f3.x, a1.z); a1.w = fmaf(w, f3.y, a1.w);
        denom += w;
    }

    float inv = 1.0f / denom;
    long base = (long)nid * HIDC + lane * 8;
    const float4* bp = (const float4*)(bias + lane * 8);
    float4 b0 = bp[0], b1 = bp[1];
    float r[8];
    r[0] = fmaxf(a0.x * inv + b0.x, 0.f);
    r[1] = fmaxf(a0.y * inv + b0.y, 0.f);
    r[2] = fmaxf(a0.z * inv + b0.z, 0.f);
    r[3] = fmaxf(a0.w * inv + b0.w, 0.f);
    r[4] = fmaxf(a1.x * inv + b1.x, 0.f);
    r[5] = fmaxf(a1.y * inv + b1.y, 0.f);
    r[6] = fmaxf(a1.z * inv + b1.z, 0.f);
    r[7] = fmaxf(a1.w * inv + b1.w, 0.f);
    if (mode == 1) {
        uint4 rv = *(const uint4*)(resid + base);
#pragma unroll
        for (int j = 0; j < 4; j++) {
            float2 q = __half22float2(((const __half2*)&rv)[j]);
            r[j * 2]     += q.x;
            r[j * 2 + 1] += q.y;
        }
    }
    __align__(16) __half hv2[8];
#pragma unroll
    for (int j = 0; j < 4; j++)
        ((__half2*)hv2)[j] = __floats2half2_rn(r[j * 2], r[j * 2 + 1]);
    *(uint4*)(out + base) = *(uint4*)hv2;
}

// ---------------- global mean pool (batch is sorted, fp16 input) -------------
#define POOL_CH 256
__global__ void pool_kernel(const __half* __restrict__ xr,
                            const int* __restrict__ batch,
                            float* pooled, float* cnt) {
    __shared__ int sb[POOL_CH];
    int b0 = blockIdx.x * POOL_CH;
    int t = threadIdx.x;
    int nmax = min(POOL_CH, NN - b0);
    if (nmax <= 0) return;
    for (int i = t; i < nmax; i += blockDim.x) sb[i] = batch[b0 + i];
    __syncthreads();

    float acc = 0.0f;
    int gcur = sb[0];
    int cstart = 0;
    for (int i = 0; i < nmax; i++) {
        int g = sb[i];
        if (g != gcur) {
            atomicAdd(&pooled[gcur * HIDC + t], acc);
            if (t == 0) atomicAdd(&cnt[gcur], (float)(i - cstart));
            acc = 0.0f; cstart = i; gcur = g;
        }
        acc += __half2float(xr[(size_t)(b0 + i) * HIDC + t]);
    }
    atomicAdd(&pooled[gcur * HIDC + t], acc);
    if (t == 0) atomicAdd(&cnt[gcur], (float)(nmax - cstart));
}

// ---------------- final FC ----------------
__global__ void fc_kernel(const float* __restrict__ pooled,
                          const float* __restrict__ cnt,
                          const float* __restrict__ fcW,
                          const float* __restrict__ fcb,
                          float* __restrict__ out) {
    int idx = blockIdx.x * blockDim.x + threadIdx.x;
    if (idx >= GG * CC) return;
    int g = idx / CC, c = idx % CC;
    float inv = 1.0f / fmaxf(cnt[g], 1.0f);
    float acc = 0.0f;
    for (int k = 0; k < HIDC; k++)
        acc = fmaf(pooled[g * HIDC + k], fcW[k * CC + c], acc);
    out[idx] = acc * inv + fcb[c];
}

// ---------------- launch ----------------
extern "C" void kernel_launch(void* const* d_in, const int* in_sizes, int n_in,
                              void* d_out, int out_size) {
    const float* x   = (const float*)d_in[0];
    const int*   ei  = (const int*)d_in[1];
    const int*   bat = (const int*)d_in[2];
    const float* W1  = (const float*)d_in[3];
    const float* as1 = (const float*)d_in[4];
    const float* ad1 = (const float*)d_in[5];
    const float* b1  = (const float*)d_in[6];
    const float* W2  = (const float*)d_in[7];
    const float* as2 = (const float*)d_in[8];
    const float* ad2 = (const float*)d_in[9];
    const float* b2  = (const float*)d_in[10];
    const float* W3  = (const float*)d_in[11];
    const float* as3 = (const float*)d_in[12];
    const float* ad3 = (const float*)d_in[13];
    const float* b3  = (const float*)d_in[14];
    const float* fcW = (const float*)d_in[15];
    const float* fcb = (const float*)d_in[16];
    float* out = (float*)d_out;

    float *pSS, *pSD, *pPool, *pCnt;
    int *pRow, *pDeg, *pPos, *pSrc;
    unsigned* pME;
    __half *pXin, *pHh, *pX1, *pX2, *pXR;
    __half *pBh1, *pBl1, *pBh2, *pBl2, *pBh3, *pBl3;
    cudaGetSymbolAddress((void**)&pXin, g_Xin);
    cudaGetSymbolAddress((void**)&pHh, g_Hh);
    cudaGetSymbolAddress((void**)&pX1, g_X1);
    cudaGetSymbolAddress((void**)&pX2, g_X2);
    cudaGetSymbolAddress((void**)&pXR, g_XR);
    cudaGetSymbolAddress((void**)&pSS, g_ssrc);
    cudaGetSymbolAddress((void**)&pSD, g_sdst);
    cudaGetSymbolAddress((void**)&pME, g_maxenc);
    cudaGetSymbolAddress((void**)&pRow, g_rowptr);
    cudaGetSymbolAddress((void**)&pDeg, g_deg);
    cudaGetSymbolAddress((void**)&pPos, g_pos);
    cudaGetSymbolAddress((void**)&pSrc, g_srcs);
    cudaGetSymbolAddress((void**)&pPool, g_pooled);
    cudaGetSymbolAddress((void**)&pCnt, g_cnt);
    cudaGetSymbolAddress((void**)&pBh1, g_Bh1);
    cudaGetSymbolAddress((void**)&pBl1, g_Bl1);
    cudaGetSymbolAddress((void**)&pBh2, g_Bh2);
    cudaGetSymbolAddress((void**)&pBl2, g_Bl2);
    cudaGetSymbolAddress((void**)&pBh3, g_Bh3);
    cudaGetSymbolAddress((void**)&pBl3, g_Bl3);

    const int GEMM_SMEM = 98304;   // 2 stages x 48KB -> 2 CTAs/SM
    cudaFuncSetAttribute(gemm_mma_kernel,
                         cudaFuncAttributeMaxDynamicSharedMemorySize, GEMM_SMEM);

    // init + CSR build + operand conversion
    zero_kernel<<<(NN + 255) / 256, 256>>>(pDeg, pPool, pCnt, pME);
    hist_kernel<<<(ETOT + 255) / 256, 256>>>(ei, pDeg, pPos);
    scan_kernel<<<1, 1024>>>(pDeg, pRow);
    scatter_kernel<<<(ETOT + 255) / 256, 256>>>(ei, pRow, pPos, pSrc);
    convert_x_kernel<<<(NN * INC + 255) / 256, 256>>>(x, pXin, NN * INC);
    convert_w_all_kernel<<<(W1ELEM + 2 * W23ELEM + 255) / 256, 256>>>(
        W1, W2, W3, pBh1, pBl1, pBh2, pBl2, pBh3, pBl3);

    const int warpBlocks = (NN * 32 + 255) / 256;
    dim3 gemmGrid((NN + 127) / 128, HIDC / 128);

    // layer 1 (K=64)
    gemm_mma_kernel<<<gemmGrid, 256, GEMM_SMEM>>>(pXin, pBh1, pBl1, pHh, INC);
    score_kernel<<<warpBlocks, 256>>>(pHh, as1, ad1, pSS, pSD, pME + 0);
    agg_kernel<<<warpBlocks, 256>>>(pHh, pSS, pSD, pME + 0, pRow, pSrc, b1, nullptr,
                                    pX1, 0);

    // layer 2 (K=256)
    gemm_mma_kernel<<<gemmGrid, 256, GEMM_SMEM>>>(pX1, pBh2, pBl2, pHh, HIDC);
    score_kernel<<<warpBlocks, 256>>>(pHh, as2, ad2, pSS, pSD, pME + 4);
    agg_kernel<<<warpBlocks, 256>>>(pHh, pSS, pSD, pME + 4, pRow, pSrc, b2, nullptr,
                                    pX2, 0);

    // layer 3 (K=256, + residual with X1)
    gemm_mma_kernel<<<gemmGrid, 256, GEMM_SMEM>>>(pX2, pBh3, pBl3, pHh, HIDC);
    score_kernel<<<warpBlocks, 256>>>(pHh, as3, ad3, pSS, pSD, pME + 8);
    agg_kernel<<<warpBlocks, 256>>>(pHh, pSS, pSD, pME + 8, pRow, pSrc, b3, pX1,
                                    pXR, 1);

    // pool + fc
    pool_kernel<<<(NN + POOL_CH - 1) / POOL_CH, 256>>>(pXR, bat, pPool, pCnt);
    fc_kernel<<<(GG * CC + 255) / 256, 256>>>(pPool, pCnt, fcW, fcb, out);
}

// round 17
// speedup vs baseline: 1.0836x; 1.0768x over previous
#include <cuda_runtime.h>
#include <cuda_bf16.h>
#include <cuda_fp16.h>
#include <math_constants.h>
#include <cstdint>

// ---------------- problem constants ----------------
#define NN    50000
#define EE    800000
#define ETOT  (EE + NN)     // edges + self loops
#define INC   64
#define HIDC  256
#define HEADS 4
#define OUTC  64
#define GG    64
#define CC    10
#define NEG_SLOPE 0.2f

// ---------------- device scratch (no allocation allowed) ----------------
__device__ __align__(16) __half g_Xin[NN * INC];   // input x in fp16
__device__ __align__(16) __half g_Hh[NN * HIDC];   // transformed features (fp16)
__device__ __align__(16) __half g_X1[NN * HIDC];   // layer1 output (resid + GEMM A)
__device__ __align__(16) __half g_X2[NN * HIDC];   // layer2 output (GEMM A)
__device__ __align__(16) __half g_XR[NN * HIDC];   // layer3 output + residual
__device__ float g_ssrc[NN * HEADS];
__device__ float g_sdst[NN * HEADS];
__device__ unsigned g_maxenc[3 * HEADS];   // per-layer per-head encoded max(ssrc)
__device__ int   g_rowptr[NN + 1];
__device__ int   g_deg[NN];
__device__ __align__(16) int g_pos[ETOT + 4];  // within-node position (from hist)
__device__ int   g_srcs[ETOT];
__device__ float g_pooled[GG * HIDC];
__device__ float g_cnt[GG];

// fp16 weights for tensor-core GEMM: Wt[n][k]
__device__ __half g_Bh1[HIDC * INC];
__device__ __half g_Bh2[HIDC * HIDC];
__device__ __half g_Bh3[HIDC * HIDC];

// ---------------- PTX helpers (sm_80-compatible: mma.sync / ldmatrix / cp.async) --
__device__ __forceinline__ uint32_t smem_to_u32(const void* p) {
    uint32_t a;
    asm("{ .reg .u64 t; cvta.to.shared.u64 t, %1; cvt.u32.u64 %0, t; }"
        : "=r"(a) : "l"(p));
    return a;
}
__device__ __forceinline__ void cp16(uint32_t dst, const void* src, uint32_t srcsize) {
    asm volatile("cp.async.cg.shared.global [%0], [%1], 16, %2;"
                 :: "r"(dst), "l"(src), "r"(srcsize));
}
#define CP_COMMIT() asm volatile("cp.async.commit_group;" ::: "memory")
#define CP_WAIT(n)  asm volatile("cp.async.wait_group %0;" :: "n"(n) : "memory")

__device__ __forceinline__ void ldm4(uint32_t* r, uint32_t addr) {
    asm volatile("ldmatrix.sync.aligned.m8n8.x4.shared.b16 {%0,%1,%2,%3}, [%4];"
        : "=r"(r[0]), "=r"(r[1]), "=r"(r[2]), "=r"(r[3]) : "r"(addr));
}
__device__ __forceinline__ void mma16816(float* c, const uint32_t* a,
                                         uint32_t b0, uint32_t b1) {
    asm volatile("mma.sync.aligned.m16n8k16.row.col.f32.f16.f16.f32 "
        "{%0,%1,%2,%3}, {%4,%5,%6,%7}, {%8,%9}, {%0,%1,%2,%3};"
        : "+f"(c[0]), "+f"(c[1]), "+f"(c[2]), "+f"(c[3])
        : "r"(a[0]), "r"(a[1]), "r"(a[2]), "r"(a[3]), "r"(b0), "r"(b1));
}

// order-preserving float<->uint encoding for atomicMax
__device__ __forceinline__ unsigned encf(float f) {
    unsigned u = __float_as_uint(f);
    return (u & 0x80000000u) ? ~u : (u | 0x80000000u);
}
__device__ __forceinline__ float decf(unsigned u) {
    return (u & 0x80000000u) ? __uint_as_float(u & 0x7FFFFFFFu)
                             : __uint_as_float(~u);
}

// ---------------- zero / init ----------------
__global__ void zero_kernel(int* deg, float* pooled, float* cnt,
                            unsigned* maxenc) {
    int i = blockIdx.x * blockDim.x + threadIdx.x;
    if (i < NN) deg[i] = 0;
    if (i < GG * HIDC) pooled[i] = 0.0f;
    if (i < GG) cnt[i] = 0.0f;
    if (i < 3 * HEADS) maxenc[i] = 0u;    // below enc of any finite float
}

// ---------------- CSR build: hist emits per-edge position -------------------
__global__ void hist_kernel(const int* __restrict__ ei, int* deg,
                            int* __restrict__ pos) {
    int e = blockIdx.x * blockDim.x + threadIdx.x;
    if (e >= ETOT) return;
    int dst = (e < EE) ? __ldg(&ei[EE + e]) : (e - EE);
    pos[e] = atomicAdd(&deg[dst], 1);
}

__global__ void scan_kernel(const int* __restrict__ deg, int* rowptr) {
    __shared__ int sm[1024];
    int t = threadIdx.x;
    const int CH = (NN + 1023) / 1024;
    int b0 = t * CH;
    int b1 = min(b0 + CH, NN);
    int s = 0;
    for (int i = b0; i < b1; i++) s += deg[i];
    sm[t] = s;
    __syncthreads();
    for (int off = 1; off < 1024; off <<= 1) {
        int v = (t >= off) ? sm[t - off] : 0;
        __syncthreads();
        sm[t] += v;
        __syncthreads();
    }
    int run = (t == 0) ? 0 : sm[t - 1];
    for (int i = b0; i < b1; i++) { rowptr[i] = run; run += deg[i]; }
    if (t == 1023) rowptr[NN] = sm[1023];
}

// atomic-free scatter: slot = rowptr[dst] + pos[e]
__global__ void scatter_kernel(const int* __restrict__ ei,
                               const int* __restrict__ rowptr,
                               const int* __restrict__ pos,
                               int* __restrict__ srcs) {
    int e = blockIdx.x * blockDim.x + threadIdx.x;
    if (e >= ETOT) return;
    int src, dst;
    if (e < EE) { src = __ldg(&ei[e]); dst = __ldg(&ei[EE + e]); }
    else        { src = e - EE; dst = e - EE; }
    srcs[__ldg(&rowptr[dst]) + __ldg(&pos[e])] = src;
}

// ---------------- fp32 -> fp16 converters ----------------
__global__ void convert_x_kernel(const float* __restrict__ x,
                                 __half* __restrict__ out, int n) {
    int i = blockIdx.x * blockDim.x + threadIdx.x;
    if (i >= n) return;
    out[i] = __float2half_rn(x[i]);
}

// All three weights in one launch: W[k][n] fp32 -> out[n][k] fp16
#define W1ELEM (INC * HIDC)
#define W23ELEM (HIDC * HIDC)
__global__ void convert_w_all_kernel(const float* __restrict__ W1,
                                     const float* __restrict__ W2,
                                     const float* __restrict__ W3,
                                     __half* __restrict__ h1,
                                     __half* __restrict__ h2,
                                     __half* __restrict__ h3) {
    int idx = blockIdx.x * blockDim.x + threadIdx.x;
    const float* W;
    __half* hi;
    int K, i;
    if (idx < W1ELEM) {
        W = W1; hi = h1; K = INC; i = idx;
    } else if (idx < W1ELEM + W23ELEM) {
        W = W2; hi = h2; K = HIDC; i = idx - W1ELEM;
    } else if (idx < W1ELEM + 2 * W23ELEM) {
        W = W3; hi = h3; K = HIDC; i = idx - W1ELEM - W23ELEM;
    } else return;
    int n = i / K, k = i - n * K;
    hi[i] = __float2half_rn(W[(size_t)k * HIDC + n]);
}

// ---------------- mma.sync fp16 GEMM: C = A*B^T, fp16 in/out ----------------
// BM=128 BN=128 BK=64, double-buffered cp.async, 8 warps (2m x 4n), 64x32/warp.
// stage: A(16K) B(16K) = 32KB; 2 stages = 64KB -> 2 CTAs/SM.
__global__ void __launch_bounds__(256, 2)
gemm_mma_kernel(const __half* __restrict__ Ah,
                const __half* __restrict__ Bh,
                __half* __restrict__ Ch, int K) {
    extern __shared__ char smem[];
    uint32_t sbase = smem_to_u32(smem);
    const int tid = threadIdx.x;
    const int lane = tid & 31, wid = tid >> 5;
    const int warp_m = wid & 1;
    const int warp_n = wid >> 1;
    const int rowBase = blockIdx.x * 128;
    const int colBase = blockIdx.y * 128;
    const int Kiters = K >> 6;

    float acc[4][4][4];
#pragma unroll
    for (int a = 0; a < 4; a++)
#pragma unroll
        for (int b = 0; b < 4; b++)
#pragma unroll
            for (int c = 0; c < 4; c++) acc[a][b][c] = 0.0f;

    auto load_stage = [&](int s, int kbase) {
        uint32_t st = sbase + s * 32768;
#pragma unroll
        for (int i = 0; i < 4; i++) {
            int p = tid + i * 256;            // 0..1023
            int r = p >> 3, ck = p & 7;
            uint32_t off = (uint32_t)((r * 8 + (ck ^ (r & 7))) * 16);
            int gr = rowBase + r;
            uint32_t sz = (gr < NN) ? 16u : 0u;
            int grc = min(gr, NN - 1);
            size_t ai = (size_t)grc * K + kbase + ck * 8;
            cp16(st + off, Ah + ai, sz);
            size_t bi = (size_t)(colBase + r) * K + kbase + ck * 8;
            cp16(st + 16384 + off, Bh + bi, 16u);
        }
    };

    load_stage(0, 0);
    CP_COMMIT();

    const int rA  = (lane & 7) + ((lane >> 3) & 1) * 8;
    const int cAb = (lane >> 4) & 1;
    const int rB  = (lane & 7) + ((lane >> 4) & 1) * 8;
    const int cBb = (lane >> 3) & 1;

    for (int kt = 0; kt < Kiters; kt++) {
        if (kt + 1 < Kiters) {
            load_stage((kt + 1) & 1, (kt + 1) * 64);
            CP_COMMIT();
            CP_WAIT(1);
        } else {
            CP_WAIT(0);
        }
        __syncthreads();

        uint32_t mb = sbase + (kt & 1) * 32768;
#pragma unroll
        for (int kh = 0; kh < 4; kh++) {
            uint32_t ah[4][4], bh[2][4];
            int cA = kh * 2 + cAb;
            int cB = kh * 2 + cBb;
#pragma unroll
            for (int mt = 0; mt < 4; mt++) {
                int row = warp_m * 64 + mt * 16 + rA;
                uint32_t ad = mb + (uint32_t)((row * 8 + (cA ^ (row & 7))) * 16);
                ldm4(ah[mt], ad);
            }
#pragma unroll
            for (int nb = 0; nb < 2; nb++) {
                int n = warp_n * 32 + nb * 16 + rB;
                uint32_t bd = mb + 16384 + (uint32_t)((n * 8 + (cB ^ (n & 7))) * 16);
                ldm4(bh[nb], bd);
            }
#pragma unroll
            for (int mt = 0; mt < 4; mt++)
#pragma unroll
                for (int nt = 0; nt < 4; nt++) {
                    int nb = nt >> 1, s2 = (nt & 1) * 2;
                    mma16816(acc[mt][nt], ah[mt], bh[nb][s2], bh[nb][s2 + 1]);
                }
        }
        __syncthreads();
    }

    // ---- epilogue: half2 stores ----
#pragma unroll
    for (int mt = 0; mt < 4; mt++) {
        int r0 = rowBase + warp_m * 64 + mt * 16 + (lane >> 2);
#pragma unroll
        for (int nt = 0; nt < 4; nt++) {
            int c0 = colBase + warp_n * 32 + nt * 8 + (lane & 3) * 2;
            if (r0 < NN)
                *(__half2*)(Ch + (size_t)r0 * HIDC + c0) =
                    __floats2half2_rn(acc[mt][nt][0], acc[mt][nt][1]);
            if (r0 + 8 < NN)
                *(__half2*)(Ch + (size_t)(r0 + 8) * HIDC + c0) =
                    __floats2half2_rn(acc[mt][nt][2], acc[mt][nt][3]);
        }
    }
}

// ---------------- attention scores per node + folded per-head global max -----
__global__ void score_kernel(const __half* __restrict__ Hh,
                             const float* __restrict__ a_s,
                             const float* __restrict__ a_d,
                             float* __restrict__ ssrc,
                             float* __restrict__ sdst,
                             unsigned* __restrict__ maxenc) {
    __shared__ unsigned smx[HEADS];
    int tid = threadIdx.x;
    if (tid < HEADS) smx[tid] = 0u;
    __syncthreads();

    int warp = (blockIdx.x * blockDim.x + tid) >> 5;
    int lane = tid & 31;
    if (warp < NN) {
        uint4 hv = *(const uint4*)(Hh + (size_t)warp * HIDC + lane * 8);
        float2 f0 = __half22float2(((const __half2*)&hv)[0]);
        float2 f1 = __half22float2(((const __half2*)&hv)[1]);
        float2 f2 = __half22float2(((const __half2*)&hv)[2]);
        float2 f3 = __half22float2(((const __half2*)&hv)[3]);
        const float4* sp = (const float4*)(a_s + lane * 8);
        float4 s0 = sp[0], s1 = sp[1];
        const float4* dp = (const float4*)(a_d + lane * 8);
        float4 d0 = dp[0], d1 = dp[1];
        float vs = f0.x * s0.x + f0.y * s0.y + f1.x * s0.z + f1.y * s0.w
                 + f2.x * s1.x + f2.y * s1.y + f3.x * s1.z + f3.y * s1.w;
        float vd = f0.x * d0.x + f0.y * d0.y + f1.x * d0.z + f1.y * d0.w
                 + f2.x * d1.x + f2.y * d1.y + f3.x * d1.z + f3.y * d1.w;
#pragma unroll
        for (int off = 4; off > 0; off >>= 1) {
            vs += __shfl_xor_sync(0xffffffffu, vs, off);
            vd += __shfl_xor_sync(0xffffffffu, vd, off);
        }
        if ((lane & 7) == 0) {
            int head = lane >> 3;
            ssrc[warp * HEADS + head] = vs;
            sdst[warp * HEADS + head] = vd;
            atomicMax(&smx[head], encf(vs));
        }
    }
    __syncthreads();
    if (tid < HEADS && smx[tid] != 0u) atomicMax(&maxenc[tid], smx[tid]);
}

// ---------------- single-pass softmax aggregation (one warp per node) --------
// lane l owns columns [l*8, l*8+8), head = l>>3.
// e <= m0 := lrelu(max_src(ssrc)+sdst), so exp(e-m0) <= 1: no rescale needed.
// mode 0: fp16 out | mode 1: fp16 out + resid
__global__ void __launch_bounds__(256)
agg_kernel(const __half* __restrict__ Hh,
           const float* __restrict__ ssrc,
           const float* __restrict__ sdst,
           const unsigned* __restrict__ maxenc,
           const int* __restrict__ rowptr,
           const int* __restrict__ srcs,
           const float* __restrict__ bias,
           const __half* __restrict__ resid,
           __half* __restrict__ out,
           int mode) {
    int nid = (blockIdx.x * blockDim.x + threadIdx.x) >> 5;
    int lane = threadIdx.x & 31;
    if (nid >= NN) return;
    int head = lane >> 3;
    size_t laneoff = (size_t)lane * 8;

    float sd = sdst[nid * HEADS + head];
    float mtv = decf(__ldg(&maxenc[head])) + sd;
    float m0 = (mtv > 0.0f) ? mtv : NEG_SLOPE * mtv;   // upper bound on e
    int beg = rowptr[nid];
    int end = rowptr[nid + 1];

    float denom = 0.0f;
    float4 a0 = make_float4(0.f, 0.f, 0.f, 0.f);
    float4 a1 = make_float4(0.f, 0.f, 0.f, 0.f);

    // depth-1 pipeline: prefetch next edge's src, score, and feature vec
    int srcN = __ldg(&srcs[beg]);
    float ssN = __ldg(&ssrc[srcN * HEADS + head]);
    uint4 hN = *(const uint4*)(Hh + (size_t)srcN * HIDC + laneoff);

    for (int i = beg; i < end; i++) {
        float ss = ssN;
        uint4 hv = hN;
        if (i + 1 < end) {
            srcN = __ldg(&srcs[i + 1]);
            ssN = __ldg(&ssrc[srcN * HEADS + head]);
            hN = *(const uint4*)(Hh + (size_t)srcN * HIDC + laneoff);
        }
        float e = ss + sd;
        e = (e > 0.0f) ? e : NEG_SLOPE * e;
        float w = __expf(e - m0);
        float2 f0 = __half22float2(((const __half2*)&hv)[0]);
        float2 f1 = __half22float2(((const __half2*)&hv)[1]);
        float2 f2 = __half22float2(((const __half2*)&hv)[2]);
        float2 f3 = __half22float2(((const __half2*)&hv)[3]);
        a0.x = fmaf(w, f0.x, a0.x); a0.y = fmaf(w, f0.y, a0.y);
        a0.z = fmaf(w, f1.x, a0.z); a0.w = fmaf(w, f1.y, a0.w);
        a1.x = fmaf(w, f2.x, a1.x); a1.y = fmaf(w, f2.y, a1.y);
        a1.z = fmaf(w, f3.x, a1.z); a1.w = fmaf(w, f3.y, a1.w);
        denom += w;
    }

    float inv = 1.0f / denom;
    long base = (long)nid * HIDC + lane * 8;
    const float4* bp = (const float4*)(bias + lane * 8);
    float4 b0 = bp[0], b1 = bp[1];
    float r[8];
    r[0] = fmaxf(a0.x * inv + b0.x, 0.f);
    r[1] = fmaxf(a0.y * inv + b0.y, 0.f);
    r[2] = fmaxf(a0.z * inv + b0.z, 0.f);
    r[3] = fmaxf(a0.w * inv + b0.w, 0.f);
    r[4] = fmaxf(a1.x * inv + b1.x, 0.f);
    r[5] = fmaxf(a1.y * inv + b1.y, 0.f);
    r[6] = fmaxf(a1.z * inv + b1.z, 0.f);
    r[7] = fmaxf(a1.w * inv + b1.w, 0.f);
    if (mode == 1) {
        uint4 rv = *(const uint4*)(resid + base);
#pragma unroll
        for (int j = 0; j < 4; j++) {
            float2 q = __half22float2(((const __half2*)&rv)[j]);
            r[j * 2]     += q.x;
            r[j * 2 + 1] += q.y;
        }
    }
    __align__(16) __half hv2[8];
#pragma unroll
    for (int j = 0; j < 4; j++)
        ((__half2*)hv2)[j] = __floats2half2_rn(r[j * 2], r[j * 2 + 1]);
    *(uint4*)(out + base) = *(uint4*)hv2;
}

// ---------------- global mean pool (batch is sorted, fp16 input) -------------
#define POOL_CH 256
__global__ void pool_kernel(const __half* __restrict__ xr,
                            const int* __restrict__ batch,
                            float* pooled, float* cnt) {
    __shared__ int sb[POOL_CH];
    int b0 = blockIdx.x * POOL_CH;
    int t = threadIdx.x;
    int nmax = min(POOL_CH, NN - b0);
    if (nmax <= 0) return;
    for (int i = t; i < nmax; i += blockDim.x) sb[i] = batch[b0 + i];
    __syncthreads();

    float acc = 0.0f;
    int gcur = sb[0];
    int cstart = 0;
    for (int i = 0; i < nmax; i++) {
        int g = sb[i];
        if (g != gcur) {
            atomicAdd(&pooled[gcur * HIDC + t], acc);
            if (t == 0) atomicAdd(&cnt[gcur], (float)(i - cstart));
            acc = 0.0f; cstart = i; gcur = g;
        }
        acc += __half2float(xr[(size_t)(b0 + i) * HIDC + t]);
    }
    atomicAdd(&pooled[gcur * HIDC + t], acc);
    if (t == 0) atomicAdd(&cnt[gcur], (float)(nmax - cstart));
}

// ---------------- final FC ----------------
__global__ void fc_kernel(const float* __restrict__ pooled,
                          const float* __restrict__ cnt,
                          const float* __restrict__ fcW,
                          const float* __restrict__ fcb,
                          float* __restrict__ out) {
    int idx = blockIdx.x * blockDim.x + threadIdx.x;
    if (idx >= GG * CC) return;
    int g = idx / CC, c = idx % CC;
    float inv = 1.0f / fmaxf(cnt[g], 1.0f);
    float acc = 0.0f;
    for (int k = 0; k < HIDC; k++)
        acc = fmaf(pooled[g * HIDC + k], fcW[k * CC + c], acc);
    out[idx] = acc * inv + fcb[c];
}

// ---------------- launch ----------------
extern "C" void kernel_launch(void* const* d_in, const int* in_sizes, int n_in,
                              void* d_out, int out_size) {
    const float* x   = (const float*)d_in[0];
    const int*   ei  = (const int*)d_in[1];
    const int*   bat = (const int*)d_in[2];
    const float* W1  = (const float*)d_in[3];
    const float* as1 = (const float*)d_in[4];
    const float* ad1 = (const float*)d_in[5];
    const float* b1  = (const float*)d_in[6];
    const float* W2  = (const float*)d_in[7];
    const float* as2 = (const float*)d_in[8];
    const float* ad2 = (const float*)d_in[9];
    const float* b2  = (const float*)d_in[10];
    const float* W3  = (const float*)d_in[11];
    const float* as3 = (const float*)d_in[12];
    const float* ad3 = (const float*)d_in[13];
    const float* b3  = (const float*)d_in[14];
    const float* fcW = (const float*)d_in[15];
    const float* fcb = (const float*)d_in[16];
    float* out = (float*)d_out;

    float *pSS, *pSD, *pPool, *pCnt;
    int *pRow, *pDeg, *pPos, *pSrc;
    unsigned* pME;
    __half *pXin, *pHh, *pX1, *pX2, *pXR;
    __half *pBh1, *pBh2, *pBh3;
    cudaGetSymbolAddress((void**)&pXin, g_Xin);
    cudaGetSymbolAddress((void**)&pHh, g_Hh);
    cudaGetSymbolAddress((void**)&pX1, g_X1);
    cudaGetSymbolAddress((void**)&pX2, g_X2);
    cudaGetSymbolAddress((void**)&pXR, g_XR);
    cudaGetSymbolAddress((void**)&pSS, g_ssrc);
    cudaGetSymbolAddress((void**)&pSD, g_sdst);
    cudaGetSymbolAddress((void**)&pME, g_maxenc);
    cudaGetSymbolAddress((void**)&pRow, g_rowptr);
    cudaGetSymbolAddress((void**)&pDeg, g_deg);
    cudaGetSymbolAddress((void**)&pPos, g_pos);
    cudaGetSymbolAddress((void**)&pSrc, g_srcs);
    cudaGetSymbolAddress((void**)&pPool, g_pooled);
    cudaGetSymbolAddress((void**)&pCnt, g_cnt);
    cudaGetSymbolAddress((void**)&pBh1, g_Bh1);
    cudaGetSymbolAddress((void**)&pBh2, g_Bh2);
    cudaGetSymbolAddress((void**)&pBh3, g_Bh3);

    const int GEMM_SMEM = 65536;   // 2 stages x 32KB -> 2 CTAs/SM
    cudaFuncSetAttribute(gemm_mma_kernel,
                         cudaFuncAttributeMaxDynamicSharedMemorySize, GEMM_SMEM);

    // init + CSR build + operand conversion
    zero_kernel<<<(NN + 255) / 256, 256>>>(pDeg, pPool, pCnt, pME);
    hist_kernel<<<(ETOT + 255) / 256, 256>>>(ei, pDeg, pPos);
    scan_kernel<<<1, 1024>>>(pDeg, pRow);
    scatter_kernel<<<(ETOT + 255) / 256, 256>>>(ei, pRow, pPos, pSrc);
    convert_x_kernel<<<(NN * INC + 255) / 256, 256>>>(x, pXin, NN * INC);
    convert_w_all_kernel<<<(W1ELEM + 2 * W23ELEM + 255) / 256, 256>>>(
        W1, W2, W3, pBh1, pBh2, pBh3);

    const int warpBlocks = (NN * 32 + 255) / 256;
    dim3 gemmGrid((NN + 127) / 128, HIDC / 128);

    // layer 1 (K=64)
    gemm_mma_kernel<<<gemmGrid, 256, GEMM_SMEM>>>(pXin, pBh1, pHh, INC);
    score_kernel<<<warpBlocks, 256>>>(pHh, as1, ad1, pSS, pSD, pME + 0);
    agg_kernel<<<warpBlocks, 256>>>(pHh, pSS, pSD, pME + 0, pRow, pSrc, b1, nullptr,
                                    pX1, 0);

    // layer 2 (K=256)
    gemm_mma_kernel<<<gemmGrid, 256, GEMM_SMEM>>>(pX1, pBh2, pHh, HIDC);
    score_kernel<<<warpBlocks, 256>>>(pHh, as2, ad2, pSS, pSD, pME + 4);
    agg_kernel<<<warpBlocks, 256>>>(pHh, pSS, pSD, pME + 4, pRow, pSrc, b2, nullptr,
                                    pX2, 0);

    // layer 3 (K=256, + residual with X1)
    gemm_mma_kernel<<<gemmGrid, 256, GEMM_SMEM>>>(pX2, pBh3, pHh, HIDC);
    score_kernel<<<warpBlocks, 256>>>(pHh, as3, ad3, pSS, pSD, pME + 8);
    agg_kernel<<<warpBlocks, 256>>>(pHh, pSS, pSD, pME + 8, pRow, pSrc, b3, pX1,
                                    pXR, 1);

    // pool + fc
    pool_kernel<<<(NN + POOL_CH - 1) / POOL_CH, 256>>>(pXR, bat, pPool, pCnt);
    fc_kernel<<<(GG * CC + 255) / 256, 256>>>(pPool, pCnt, fcW, fcb, out);
}